// round 17
// baseline (speedup 1.0000x reference)
#include <cuda_runtime.h>
#include <cuda_bf16.h>
#include <cstdint>

#define NN 100000
#define EE 800000
#define ET (EE + NN)
#define GG 256
#define FD 128

// ------------------------- scratch (static device globals; no allocs) ------
__device__ float g_hpA[(size_t)NN * FD];   // hp slot 0
__device__ float g_hpB[(size_t)NN * FD];   // hp slot 1 / final layer out
__device__ float g_als[NN * 4];            // logits slot 0
__device__ float g_ald[NN * 4];
__device__ float g_als2[NN * 4];           // logits slot 1
__device__ float g_ald2[NN * 4];
__device__ int   g_deg[NN];
__device__ int   g_rowptr[NN + 1];
__device__ int   g_cursor[NN];
__device__ int   g_csr[ET];
__device__ int   g_bsum[128];
__device__ __nv_bfloat16 g_Ahi[(size_t)NN * FD];   // layer-0 input split
__device__ __nv_bfloat16 g_Alo[(size_t)NN * FD];
__device__ __nv_bfloat16 g_Whi[3 * 128 * 128];     // per-layer W slots
__device__ __nv_bfloat16 g_Wlo[3 * 128 * 128];

// ---------------------------- PTX helpers ---------------------------------
__device__ __forceinline__ uint32_t smem_to_u32(const void* p) {
    uint32_t a;
    asm("{ .reg .u64 t; cvta.to.shared.u64 t, %1; cvt.u32.u64 %0, t; }"
        : "=r"(a) : "l"(p));
    return a;
}
__device__ __forceinline__ void ldsm4(uint32_t* r, uint32_t addr) {
    asm volatile("ldmatrix.sync.aligned.m8n8.x4.shared.b16 {%0,%1,%2,%3}, [%4];"
                 : "=r"(r[0]), "=r"(r[1]), "=r"(r[2]), "=r"(r[3]) : "r"(addr));
}
__device__ __forceinline__ void mma16816(float* c, const uint32_t* a,
                                         const uint32_t* b) {
    asm volatile(
        "mma.sync.aligned.m16n8k16.row.col.f32.bf16.bf16.f32 "
        "{%0,%1,%2,%3}, {%4,%5,%6,%7}, {%8,%9}, {%0,%1,%2,%3};"
        : "+f"(c[0]), "+f"(c[1]), "+f"(c[2]), "+f"(c[3])
        : "r"(a[0]), "r"(a[1]), "r"(a[2]), "r"(a[3]), "r"(b[0]), "r"(b[1]));
}
__device__ __forceinline__ void cpasync16(uint32_t dst, const void* src) {
    asm volatile("cp.async.cg.shared.global [%0], [%1], 16;"
                 :: "r"(dst), "l"(src));
}

// ------------------------------ CSR build ---------------------------------
__global__ void k_deg_init() {
    int i = blockIdx.x * blockDim.x + threadIdx.x;
    if (i < NN) g_deg[i] = 1;
}
__global__ void k_count(const int* __restrict__ ei) {
    int e = blockIdx.x * blockDim.x + threadIdx.x;
    if (e < EE) atomicAdd(&g_deg[ei[EE + e]], 1);
}
__global__ void k_scan1() {
    __shared__ int sh[1024];
    int tid = threadIdx.x;
    int i = blockIdx.x * 1024 + tid;
    int v = (i < NN) ? g_deg[i] : 0;
    sh[tid] = v;
    __syncthreads();
#pragma unroll
    for (int off = 1; off < 1024; off <<= 1) {
        int t = (tid >= off) ? sh[tid - off] : 0;
        __syncthreads();
        sh[tid] += t;
        __syncthreads();
    }
    if (i < NN) g_rowptr[i] = sh[tid] - v;
    if (tid == 1023) g_bsum[blockIdx.x] = sh[tid];
}
__global__ void k_scan2(int nb) {
    __shared__ int sh[128];
    int tid = threadIdx.x;
    sh[tid] = (tid < nb) ? g_bsum[tid] : 0;
    __syncthreads();
    if (tid == 0) {
        int run = 0;
        for (int i = 0; i < nb; i++) { int t = sh[i]; sh[i] = run; run += t; }
    }
    __syncthreads();
    if (tid < nb) g_bsum[tid] = sh[tid];
}
__global__ void k_scan3() {
    int i = blockIdx.x * blockDim.x + threadIdx.x;
    if (i < NN) {
        int r = g_rowptr[i] + g_bsum[i >> 10];
        g_rowptr[i] = r;
        g_cursor[i] = r;
    }
    if (i == 0) g_rowptr[NN] = ET;
}
__global__ void k_fill(const int* __restrict__ ei) {
    int t = blockIdx.x * blockDim.x + threadIdx.x;
    if (t < EE) {
        int s = ei[t], d = ei[EE + t];
        int slot = atomicAdd(&g_cursor[d], 1);
        g_csr[slot] = s;
    } else if (t < ET) {
        int n = t - EE;
        int slot = atomicAdd(&g_cursor[n], 1);
        g_csr[slot] = n;
    }
}
__global__ void k_sortseg() {
    int n = blockIdx.x * blockDim.x + threadIdx.x;
    if (n >= NN) return;
    int b = g_rowptr[n], e = g_rowptr[n + 1];
    for (int i = b + 1; i < e; i++) {
        int v = g_csr[i];
        int j = i - 1;
        while (j >= b && g_csr[j] > v) { g_csr[j + 1] = g_csr[j]; j--; }
        g_csr[j + 1] = v;
    }
}

// ----------------------- bf16 split kernels -------------------------------
__global__ void k_xsplit(const float* __restrict__ x) {
    int i = blockIdx.x * blockDim.x + threadIdx.x;
    if (i < NN * 64) {
        float v = x[i];
        __nv_bfloat16 h = __float2bfloat16(v);
        g_Ahi[i] = h;
        g_Alo[i] = __float2bfloat16(v - __bfloat162float(h));
    }
}
__global__ void k_wsplit(const float* __restrict__ W, int ne, int slot) {
    int i = blockIdx.x * blockDim.x + threadIdx.x;
    if (i < ne) {
        float v = W[i];
        __nv_bfloat16 h = __float2bfloat16(v);
        g_Whi[slot * 128 * 128 + i] = h;
        g_Wlo[slot * 128 * 128 + i] = __float2bfloat16(v - __bfloat162float(h));
    }
}

// ------- layer-0 GEMM (K=64): A from g_Ahi/g_Alo, W resident --------------
template <int K>
__global__ void __launch_bounds__(256, 2)
k_gemm_mma(const float* __restrict__ asrc, const float* __restrict__ adst,
           int wslot) {
    extern __shared__ char sm[];
    constexpr int CH = K / 64;
    constexpr int NITER = 2 * CH;
    constexpr int SROW_A = 144;
    constexpr int STG_A = 128 * SROW_A;
    constexpr int NST = 2;
    constexpr int SROW_W = K * 2 + 16;
    constexpr int WOFF = NST * STG_A;
    constexpr int WSZ = 128 * SROW_W;

    int tid = threadIdx.x, lid = tid & 31, wid = tid >> 5;
    int wm = wid >> 2, wn = wid & 3;
    int row0 = blockIdx.x * 128;
    uint32_t sb = smem_to_u32(sm);
    uint32_t sw = sb + WOFF;
    const __nv_bfloat16* Whi = g_Whi + wslot * 128 * 128;
    const __nv_bfloat16* Wlo = g_Wlo + wslot * 128 * 128;

#pragma unroll
    for (int i = tid; i < 128 * (K / 8); i += 256) {
        int r = i / (K / 8), c = (i % (K / 8)) * 8;
        cpasync16(sw + r * SROW_W + c * 2, &Whi[r * K + c]);
        cpasync16(sw + WSZ + r * SROW_W + c * 2, &Wlo[r * K + c]);
    }
    asm volatile("cp.async.commit_group;");

    auto issue = [&](int j) {
        const __nv_bfloat16* Ab = (j < CH) ? g_Ahi : g_Alo;
        int kc = (j % CH) * 64;
        uint32_t st = sb + (j % NST) * STG_A;
#pragma unroll
        for (int u = 0; u < 4; u++) {
            int i = tid + u * 256;
            int r = i >> 3, q = i & 7;
            int gr = row0 + r; if (gr >= NN) gr = NN - 1;
            cpasync16(st + r * SROW_A + q * 16,
                      &Ab[(size_t)gr * K + kc + q * 8]);
        }
        asm volatile("cp.async.commit_group;");
    };

    issue(0);
    if (NITER > 1) issue(1);

    float acc[4][4][4];
#pragma unroll
    for (int a = 0; a < 4; a++)
#pragma unroll
        for (int b = 0; b < 4; b++)
#pragma unroll
            for (int cc = 0; cc < 4; cc++) acc[a][b][cc] = 0.f;

    int arow = lid & 15;
    int ak   = (lid >> 4) * 8;
    int brow = (lid & 7) + ((lid >> 4) & 1) * 8;
    int bk   = (lid & 8) ? 8 : 0;

#pragma unroll
    for (int j = 0; j < NITER; j++) {
        if (j + 1 < NITER)
            asm volatile("cp.async.wait_group 1;" ::: "memory");
        else
            asm volatile("cp.async.wait_group 0;" ::: "memory");
        __syncthreads();
        uint32_t Abase = sb + (j % NST) * STG_A;
        int kc = (j % CH) * 64;
        bool hi = (j < CH);
#pragma unroll
        for (int kt = 0; kt < 4; kt++) {
            uint32_t afr[4][4], bh[2][4];
#pragma unroll
            for (int mt = 0; mt < 4; mt++)
                ldsm4(afr[mt], Abase + (wm * 64 + mt * 16 + arow) * SROW_A
                               + (kt * 16 + ak) * 2);
#pragma unroll
            for (int np = 0; np < 2; np++)
                ldsm4(bh[np], sw + (wn * 32 + np * 16 + brow) * SROW_W
                              + (kc + kt * 16 + bk) * 2);
#pragma unroll
            for (int mt = 0; mt < 4; mt++)
#pragma unroll
                for (int nt = 0; nt < 4; nt++)
                    mma16816(acc[mt][nt], afr[mt], &bh[nt >> 1][(nt & 1) * 2]);
            if (hi) {
                uint32_t bl[2][4];
#pragma unroll
                for (int np = 0; np < 2; np++)
                    ldsm4(bl[np], sw + WSZ + (wn * 32 + np * 16 + brow) * SROW_W
                                  + (kc + kt * 16 + bk) * 2);
#pragma unroll
                for (int mt = 0; mt < 4; mt++)
#pragma unroll
                    for (int nt = 0; nt < 4; nt++)
                        mma16816(acc[mt][nt], afr[mt], &bl[nt >> 1][(nt & 1) * 2]);
            }
        }
        if (j + 2 < NITER) {
            __syncthreads();
            issue(j + 2);
        }
    }

    // epilogue: hp slot 0 + logits slot 0
    int g = lid >> 2, q = lid & 3;
    float asv[8], adv[8];
#pragma unroll
    for (int nt = 0; nt < 4; nt++)
#pragma unroll
        for (int j = 0; j < 2; j++) {
            int col = wn * 32 + nt * 8 + q * 2 + j;
            asv[nt * 2 + j] = asrc[col];
            adv[nt * 2 + j] = adst[col];
        }
#pragma unroll
    for (int mt = 0; mt < 4; mt++) {
#pragma unroll
        for (int half = 0; half < 2; half++) {
            int row = row0 + wm * 64 + mt * 16 + g + half * 8;
            float ps = 0.f, pd = 0.f;
#pragma unroll
            for (int nt = 0; nt < 4; nt++) {
                float c0 = acc[mt][nt][half * 2];
                float c1 = acc[mt][nt][half * 2 + 1];
                if (row < NN)
                    *(float2*)&g_hpA[(size_t)row * FD + wn * 32 + nt * 8 + q * 2] =
                        make_float2(c0, c1);
                ps = fmaf(c0, asv[nt * 2], fmaf(c1, asv[nt * 2 + 1], ps));
                pd = fmaf(c0, adv[nt * 2], fmaf(c1, adv[nt * 2 + 1], pd));
            }
            ps += __shfl_xor_sync(0xffffffffu, ps, 1);
            ps += __shfl_xor_sync(0xffffffffu, ps, 2);
            pd += __shfl_xor_sync(0xffffffffu, pd, 1);
            pd += __shfl_xor_sync(0xffffffffu, pd, 2);
            if (q == 0 && row < NN) {
                g_als[row * 4 + wn] = ps;
                g_ald[row * 4 + wn] = pd;
            }
        }
    }
}

// ---------- FUSED aggregate + GEMM (K=128) for interior boundaries --------
// phase 1: each block aggregates its 128 rows (8 warps x 16 nodes, unroll-4),
//          applies bias+relu, writes bf16 hi/lo DIRECTLY into smem A tiles.
// phase 2: GEMM with A resident (stride 272) and W streamed in 4 stages:
//          (Whi,0),(Whi,64),(Wlo,0),(Wlo,64).
// io=0: read hp/als/ald slot0, write slot1.  io=1: the reverse.
__global__ void __launch_bounds__(256, 2)
k_agg_gemm(const float* __restrict__ bias,
           const float* __restrict__ asrc, const float* __restrict__ adst,
           int wslot, int io) {
    extern __shared__ char sm[];
    constexpr int K = 128;
    constexpr int SROW_AR = 272;            // resident A row stride
    constexpr int ASZ = 128 * SROW_AR;      // 34816
    constexpr int WST = 2 * ASZ;            // 69632: W stage base
    constexpr int SROW_WS = 144;
    constexpr int WSTG = 128 * SROW_WS;     // 18432

    int tid = threadIdx.x, lid = tid & 31, wid = tid >> 5;
    int wm = wid >> 2, wn = wid & 3;
    int row0 = blockIdx.x * 128;
    uint32_t sb = smem_to_u32(sm);

    const float* hp_in  = io ? g_hpB  : g_hpA;
    const float* als_in = io ? g_als2 : g_als;
    const float* ald_in = io ? g_ald2 : g_ald;
    float* hp_out       = io ? g_hpA  : g_hpB;
    float* als_out      = io ? g_als  : g_als2;
    float* ald_out      = io ? g_ald  : g_ald2;
    const __nv_bfloat16* Whi = g_Whi + wslot * 128 * 128;
    const __nv_bfloat16* Wlo = g_Wlo + wslot * 128 * 128;

    // W stage j: sel = (j<2 ? hi : lo), kc = (j&1)*64, slot = j&1
    // FIXED: full 128 rows x 64 cols per stage = 1024 cp.asyncs (8 x 16B/row)
    auto issueW = [&](int j) {
        const __nv_bfloat16* Wb = (j < 2) ? Whi : Wlo;
        int kc = (j & 1) * 64;
        uint32_t st = sb + WST + (j & 1) * WSTG;
#pragma unroll
        for (int u = 0; u < 4; u++) {
            int i = tid + u * 256;
            int r = i >> 3, q = i & 7;
            cpasync16(st + r * SROW_WS + q * 16, &Wb[r * K + kc + q * 8]);
        }
        asm volatile("cp.async.commit_group;");
    };
    issueW(0);
    issueW(1);

    // ---- phase 1: aggregate 16 nodes per warp into resident A tiles ----
    {
        int h = lid >> 3, hh = lid & 3;
        float4 b4 = *(const float4*)&bias[lid * 4];
        for (int t = 0; t < 16; t++) {
            int rl = wid * 16 + t;
            int n = row0 + rl;
            __nv_bfloat162* phi = (__nv_bfloat162*)(sm + rl * SROW_AR + lid * 8);
            __nv_bfloat162* plo = (__nv_bfloat162*)(sm + ASZ + rl * SROW_AR + lid * 8);
            if (n >= NN) {
                __nv_bfloat162 z = __floats2bfloat162_rn(0.f, 0.f);
                phi[0] = z; phi[1] = z; plo[0] = z; plo[1] = z;
                continue;
            }
            int beg = g_rowptr[n], end = g_rowptr[n + 1];
            float mx = -1e30f;
            for (int jj = beg + (lid >> 2); jj < end; jj += 8)
                mx = fmaxf(mx, als_in[g_csr[jj] * 4 + hh]);
            mx = fmaxf(mx, __shfl_xor_sync(0xffffffffu, mx, 16));
            mx = fmaxf(mx, __shfl_xor_sync(0xffffffffu, mx, 8));
            mx = fmaxf(mx, __shfl_xor_sync(0xffffffffu, mx, 4));
            float mh_own = __shfl_sync(0xffffffffu, mx, h);
            float ad_own = ald_in[n * 4 + h];
            float mh = mh_own + ad_own;
            mh = (mh > 0.f) ? mh : 0.2f * mh;

            float s = 0.f, ax = 0.f, ay = 0.f, az = 0.f, aw = 0.f;
            int jj = beg;
            for (; jj + 4 <= end; jj += 4) {
                int s0 = g_csr[jj], s1 = g_csr[jj + 1];
                int s2 = g_csr[jj + 2], s3 = g_csr[jj + 3];
                float e0 = als_in[s0 * 4 + h];
                float e1 = als_in[s1 * 4 + h];
                float e2 = als_in[s2 * 4 + h];
                float e3 = als_in[s3 * 4 + h];
                float4 v0 = *(const float4*)&hp_in[(size_t)s0 * FD + lid * 4];
                float4 v1 = *(const float4*)&hp_in[(size_t)s1 * FD + lid * 4];
                float4 v2 = *(const float4*)&hp_in[(size_t)s2 * FD + lid * 4];
                float4 v3 = *(const float4*)&hp_in[(size_t)s3 * FD + lid * 4];
                e0 += ad_own; e0 = (e0 > 0.f) ? e0 : 0.2f * e0;
                float p0 = __expf(e0 - mh);
                e1 += ad_own; e1 = (e1 > 0.f) ? e1 : 0.2f * e1;
                float p1 = __expf(e1 - mh);
                e2 += ad_own; e2 = (e2 > 0.f) ? e2 : 0.2f * e2;
                float p2 = __expf(e2 - mh);
                e3 += ad_own; e3 = (e3 > 0.f) ? e3 : 0.2f * e3;
                float p3 = __expf(e3 - mh);
                ax = fmaf(p0, v0.x, ax); ay = fmaf(p0, v0.y, ay);
                az = fmaf(p0, v0.z, az); aw = fmaf(p0, v0.w, aw); s += p0;
                ax = fmaf(p1, v1.x, ax); ay = fmaf(p1, v1.y, ay);
                az = fmaf(p1, v1.z, az); aw = fmaf(p1, v1.w, aw); s += p1;
                ax = fmaf(p2, v2.x, ax); ay = fmaf(p2, v2.y, ay);
                az = fmaf(p2, v2.z, az); aw = fmaf(p2, v2.w, aw); s += p2;
                ax = fmaf(p3, v3.x, ax); ay = fmaf(p3, v3.y, ay);
                az = fmaf(p3, v3.z, az); aw = fmaf(p3, v3.w, aw); s += p3;
            }
            for (; jj < end; jj++) {
                int s0 = g_csr[jj];
                float e0 = als_in[s0 * 4 + h] + ad_own;
                e0 = (e0 > 0.f) ? e0 : 0.2f * e0;
                float p0 = __expf(e0 - mh);
                float4 v0 = *(const float4*)&hp_in[(size_t)s0 * FD + lid * 4];
                ax = fmaf(p0, v0.x, ax); ay = fmaf(p0, v0.y, ay);
                az = fmaf(p0, v0.z, az); aw = fmaf(p0, v0.w, aw); s += p0;
            }
            float inv = 1.f / (s + 1e-16f);
            float ox = fmaxf(fmaf(ax, inv, b4.x), 0.f);
            float oy = fmaxf(fmaf(ay, inv, b4.y), 0.f);
            float oz = fmaxf(fmaf(az, inv, b4.z), 0.f);
            float ow = fmaxf(fmaf(aw, inv, b4.w), 0.f);
            __nv_bfloat162 h01 = __floats2bfloat162_rn(ox, oy);
            __nv_bfloat162 h23 = __floats2bfloat162_rn(oz, ow);
            phi[0] = h01;
            phi[1] = h23;
            plo[0] = __floats2bfloat162_rn(ox - __bfloat162float(h01.x),
                                           oy - __bfloat162float(h01.y));
            plo[1] = __floats2bfloat162_rn(oz - __bfloat162float(h23.x),
                                           ow - __bfloat162float(h23.y));
        }
    }

    // ---- phase 2: GEMM (A resident, W streamed) ----
    float acc[4][4][4];
#pragma unroll
    for (int a = 0; a < 4; a++)
#pragma unroll
        for (int b = 0; b < 4; b++)
#pragma unroll
            for (int cc = 0; cc < 4; cc++) acc[a][b][cc] = 0.f;

    int arow = lid & 15;
    int ak   = (lid >> 4) * 8;
    int brow = (lid & 7) + ((lid >> 4) & 1) * 8;
    int bk   = (lid & 8) ? 8 : 0;

#pragma unroll
    for (int j = 0; j < 4; j++) {
        if (j + 1 < 4)
            asm volatile("cp.async.wait_group 1;" ::: "memory");
        else
            asm volatile("cp.async.wait_group 0;" ::: "memory");
        __syncthreads();
        uint32_t Wbase = sb + WST + (j & 1) * WSTG;
        int kc = (j & 1) * 64;
        bool sel_hi = (j < 2);   // W selector: hi stages pair with BOTH A terms
#pragma unroll
        for (int kt = 0; kt < 4; kt++) {
            uint32_t ahi[4][4], wfr[2][4];
#pragma unroll
            for (int mt = 0; mt < 4; mt++)
                ldsm4(ahi[mt], sb + (wm * 64 + mt * 16 + arow) * SROW_AR
                               + (kc + kt * 16 + ak) * 2);
#pragma unroll
            for (int np = 0; np < 2; np++)
                ldsm4(wfr[np], Wbase + (wn * 32 + np * 16 + brow) * SROW_WS
                               + (kt * 16 + bk) * 2);
#pragma unroll
            for (int mt = 0; mt < 4; mt++)
#pragma unroll
                for (int nt = 0; nt < 4; nt++)
                    mma16816(acc[mt][nt], ahi[mt], &wfr[nt >> 1][(nt & 1) * 2]);
            if (sel_hi) {   // Alo x Whi
                uint32_t alo[4][4];
#pragma unroll
                for (int mt = 0; mt < 4; mt++)
                    ldsm4(alo[mt], sb + ASZ + (wm * 64 + mt * 16 + arow) * SROW_AR
                                   + (kc + kt * 16 + ak) * 2);
#pragma unroll
                for (int mt = 0; mt < 4; mt++)
#pragma unroll
                    for (int nt = 0; nt < 4; nt++)
                        mma16816(acc[mt][nt], alo[mt], &wfr[nt >> 1][(nt & 1) * 2]);
            }
        }
        if (j + 2 < 4) {
            __syncthreads();
            issueW(j + 2);
        }
    }

    // ---- epilogue: hp_out + logits out ----
    int g = lid >> 2, q = lid & 3;
    float asv[8], adv[8];
#pragma unroll
    for (int nt = 0; nt < 4; nt++)
#pragma unroll
        for (int j = 0; j < 2; j++) {
            int col = wn * 32 + nt * 8 + q * 2 + j;
            asv[nt * 2 + j] = asrc[col];
            adv[nt * 2 + j] = adst[col];
        }
#pragma unroll
    for (int mt = 0; mt < 4; mt++) {
#pragma unroll
        for (int half = 0; half < 2; half++) {
            int row = row0 + wm * 64 + mt * 16 + g + half * 8;
            float ps = 0.f, pd = 0.f;
#pragma unroll
            for (int nt = 0; nt < 4; nt++) {
                float c0 = acc[mt][nt][half * 2];
                float c1 = acc[mt][nt][half * 2 + 1];
                if (row < NN)
                    *(float2*)&hp_out[(size_t)row * FD + wn * 32 + nt * 8 + q * 2] =
                        make_float2(c0, c1);
                ps = fmaf(c0, asv[nt * 2], fmaf(c1, asv[nt * 2 + 1], ps));
                pd = fmaf(c0, adv[nt * 2], fmaf(c1, adv[nt * 2 + 1], pd));
            }
            ps += __shfl_xor_sync(0xffffffffu, ps, 1);
            ps += __shfl_xor_sync(0xffffffffu, ps, 2);
            pd += __shfl_xor_sync(0xffffffffu, pd, 1);
            pd += __shfl_xor_sync(0xffffffffu, pd, 2);
            if (q == 0 && row < NN) {
                als_out[row * 4 + wn] = ps;
                ald_out[row * 4 + wn] = pd;
            }
        }
    }
}

// ----------- final-layer aggregation (slot0 -> g_hpB, no relu) ------------
__global__ void __launch_bounds__(256)
k_aggregate(const float* __restrict__ bias) {
    int n = (blockIdx.x * blockDim.x + threadIdx.x) >> 5;
    if (n >= NN) return;
    int lane = threadIdx.x & 31;
    int h = lane >> 3;
    int hh = lane & 3;
    int beg = g_rowptr[n], end = g_rowptr[n + 1];

    float mx = -1e30f;
    for (int j = beg + (lane >> 2); j < end; j += 8)
        mx = fmaxf(mx, g_als[g_csr[j] * 4 + hh]);
    mx = fmaxf(mx, __shfl_xor_sync(0xffffffffu, mx, 16));
    mx = fmaxf(mx, __shfl_xor_sync(0xffffffffu, mx, 8));
    mx = fmaxf(mx, __shfl_xor_sync(0xffffffffu, mx, 4));
    float mh_own = __shfl_sync(0xffffffffu, mx, h);
    float ad_own = g_ald[n * 4 + h];
    float mh = mh_own + ad_own;
    mh = (mh > 0.f) ? mh : 0.2f * mh;

    float s = 0.f, ax = 0.f, ay = 0.f, az = 0.f, aw = 0.f;
    int j = beg;
    for (; j + 4 <= end; j += 4) {
        int s0 = g_csr[j], s1 = g_csr[j + 1];
        int s2 = g_csr[j + 2], s3 = g_csr[j + 3];
        float e0 = g_als[s0 * 4 + h];
        float e1 = g_als[s1 * 4 + h];
        float e2 = g_als[s2 * 4 + h];
        float e3 = g_als[s3 * 4 + h];
        float4 v0 = *(const float4*)&g_hpA[(size_t)s0 * FD + lane * 4];
        float4 v1 = *(const float4*)&g_hpA[(size_t)s1 * FD + lane * 4];
        float4 v2 = *(const float4*)&g_hpA[(size_t)s2 * FD + lane * 4];
        float4 v3 = *(const float4*)&g_hpA[(size_t)s3 * FD + lane * 4];
        e0 += ad_own; e0 = (e0 > 0.f) ? e0 : 0.2f * e0;
        float p0 = __expf(e0 - mh);
        e1 += ad_own; e1 = (e1 > 0.f) ? e1 : 0.2f * e1;
        float p1 = __expf(e1 - mh);
        e2 += ad_own; e2 = (e2 > 0.f) ? e2 : 0.2f * e2;
        float p2 = __expf(e2 - mh);
        e3 += ad_own; e3 = (e3 > 0.f) ? e3 : 0.2f * e3;
        float p3 = __expf(e3 - mh);
        ax = fmaf(p0, v0.x, ax); ay = fmaf(p0, v0.y, ay);
        az = fmaf(p0, v0.z, az); aw = fmaf(p0, v0.w, aw); s += p0;
        ax = fmaf(p1, v1.x, ax); ay = fmaf(p1, v1.y, ay);
        az = fmaf(p1, v1.z, az); aw = fmaf(p1, v1.w, aw); s += p1;
        ax = fmaf(p2, v2.x, ax); ay = fmaf(p2, v2.y, ay);
        az = fmaf(p2, v2.z, az); aw = fmaf(p2, v2.w, aw); s += p2;
        ax = fmaf(p3, v3.x, ax); ay = fmaf(p3, v3.y, ay);
        az = fmaf(p3, v3.z, az); aw = fmaf(p3, v3.w, aw); s += p3;
    }
    for (; j < end; j++) {
        int s0 = g_csr[j];
        float e0 = g_als[s0 * 4 + h] + ad_own;
        e0 = (e0 > 0.f) ? e0 : 0.2f * e0;
        float p0 = __expf(e0 - mh);
        float4 v0 = *(const float4*)&g_hpA[(size_t)s0 * FD + lane * 4];
        ax = fmaf(p0, v0.x, ax); ay = fmaf(p0, v0.y, ay);
        az = fmaf(p0, v0.z, az); aw = fmaf(p0, v0.w, aw); s += p0;
    }
    float inv = 1.f / (s + 1e-16f);
    float4 b4 = *(const float4*)&bias[lane * 4];
    *(float4*)&g_hpB[(size_t)n * FD + lane * 4] =
        make_float4(fmaf(ax, inv, b4.x), fmaf(ay, inv, b4.y),
                    fmaf(az, inv, b4.z), fmaf(aw, inv, b4.w));
}

// -------------------- global mean pool (batch is sorted) ------------------
__device__ __forceinline__ int lowbound(const int* __restrict__ a, int n, int key) {
    int lo = 0, hi = n;
    while (lo < hi) {
        int mid = (lo + hi) >> 1;
        if (a[mid] < key) lo = mid + 1; else hi = mid;
    }
    return lo;
}
__global__ void k_pool(const int* __restrict__ batch, float* __restrict__ out) {
    __shared__ int sb, se;
    int g = blockIdx.x;
    if (threadIdx.x == 0) {
        sb = lowbound(batch, NN, g);
        se = lowbound(batch, NN, g + 1);
    }
    __syncthreads();
    int b = sb, e = se;
    float acc = 0.f;
    for (int nidx = b; nidx < e; nidx++)
        acc += g_hpB[(size_t)nidx * FD + threadIdx.x];
    float c = (float)(e - b);
    out[g * FD + threadIdx.x] = acc / fmaxf(c, 1.f);
}

// ------------------------------- driver -----------------------------------
extern "C" void kernel_launch(void* const* d_in, const int* in_sizes, int n_in,
                              void* d_out, int out_size) {
    const float* x     = (const float*)d_in[0];
    const int*   ei    = (const int*)d_in[1];
    const int*   batch = (const int*)d_in[3];
    const float* W0 = (const float*)d_in[4];
    const float* as0 = (const float*)d_in[5];
    const float* ad0 = (const float*)d_in[6];
    const float* b0 = (const float*)d_in[7];
    const float* W1 = (const float*)d_in[8];
    const float* as1 = (const float*)d_in[9];
    const float* ad1 = (const float*)d_in[10];
    const float* b1 = (const float*)d_in[11];
    const float* W2 = (const float*)d_in[12];
    const float* as2 = (const float*)d_in[13];
    const float* ad2 = (const float*)d_in[14];
    const float* b2 = (const float*)d_in[15];
    float* out = (float*)d_out;

    const int SMEM64   = 2 * 18432 + 2 * 128 * (64 * 2 + 16);   // 73728
    const int SMEMFUSE = 2 * 34816 + 2 * 18432;                 // 106496
    cudaFuncSetAttribute(k_gemm_mma<64>,
                         cudaFuncAttributeMaxDynamicSharedMemorySize, SMEM64);
    cudaFuncSetAttribute(k_agg_gemm,
                         cudaFuncAttributeMaxDynamicSharedMemorySize, SMEMFUSE);

    const int TILES = (NN + 127) / 128;           // 782
    const int AGG_GRID = (NN * 32 + 255) / 256;   // 12500

    // side stream for the CSR build; fork-join via events (graph-capturable)
    cudaStream_t s2;
    cudaStreamCreate(&s2);
    cudaEvent_t evF, evJ;
    cudaEventCreateWithFlags(&evF, cudaEventDisableTiming);
    cudaEventCreateWithFlags(&evJ, cudaEventDisableTiming);
    cudaEventRecord(evF, 0);
    cudaStreamWaitEvent(s2, evF, 0);

    // main chain (stream 0): splits + layer-0 GEMM; CSR on s2 in parallel
    k_xsplit<<<(NN * 64 + 255) / 256, 256>>>(x);
    k_wsplit<<<(128 * 64 + 255) / 256, 256>>>(W0, 128 * 64, 0);
    k_deg_init<<<(NN + 255) / 256, 256, 0, s2>>>();
    k_gemm_mma<64><<<TILES, 256, SMEM64>>>(as0, ad0, 0);      // launch idx 3
    k_count<<<(EE + 255) / 256, 256, 0, s2>>>(ei);
    k_scan1<<<(NN + 1023) / 1024, 1024, 0, s2>>>();
    k_scan2<<<1, 128, 0, s2>>>((NN + 1023) / 1024);
    k_scan3<<<(NN + 255) / 256, 256, 0, s2>>>();
    k_fill<<<(ET + 255) / 256, 256, 0, s2>>>(ei);
    k_sortseg<<<(NN + 255) / 256, 256, 0, s2>>>();
    k_wsplit<<<(128 * 128 + 255) / 256, 256>>>(W1, 128 * 128, 1);
    k_wsplit<<<(128 * 128 + 255) / 256, 256>>>(W2, 128 * 128, 2);
    cudaEventRecord(evJ, s2);
    cudaStreamWaitEvent(0, evJ, 0);

    // fused boundaries + final aggregate + pool
    k_agg_gemm<<<TILES, 256, SMEMFUSE>>>(b0, as1, ad1, 1, 0); // agg0 + gemm1
    k_agg_gemm<<<TILES, 256, SMEMFUSE>>>(b1, as2, ad2, 2, 1); // agg1 + gemm2
    k_aggregate<<<AGG_GRID, 256>>>(b2);                        // agg2 -> hpB
    k_pool<<<GG, FD>>>(batch, out);
}